// round 2
// baseline (speedup 1.0000x reference)
#include <cuda_runtime.h>
#include <math.h>

// Problem constants
#define BB   16      // batch
#define CI   2048    // input capsules
#define NI   16      // input capsule dim
#define CJ   64      // output capsules
#define NJ   32      // output capsule dim
#define JM   2048    // CJ*NJ
#define K1_CHUNK 4   // i's per K1 block (prefix-sum chunk length)
#define K1_NBLK  (CI / K1_CHUNK)          // 512
#define RT_ICHUNK 64                      // i's per routing block (multiple of K1_CHUNK)
#define RT_NIB    (CI / RT_ICHUNK)        // 32

// Scratch in device globals (allocation-free kernel_launch).
// g_U holds chunk-local PREFIX sums of u over i within each K1 chunk:
//   for i with i%4==c, P[i] = sum_{i' in [i-c, i]} u[i']   (layout [i][b][jm])
static __device__ float g_U[(size_t)CI * BB * JM];   // 268 MB
static __device__ float g_s[BB * JM];                // s accumulator (BSS zero at start)
static __device__ float g_v[BB * JM];                // squashed v
static __device__ float g_bl[(size_t)BB * CI * CJ];  // routing logits b  [b][i][j]

// ---------------------------------------------------------------------------
// K1: compute u[b,i,jm] = sum_n x[b,i,n] * w[i,n,jm]; write chunk-local
// prefix sums over i (never reset acc within the 4-i chunk).
// Grid: 512 blocks (one 4-i chunk each), 512 threads (one jm-quad each).
// ---------------------------------------------------------------------------
__global__ void __launch_bounds__(512) k_u_prefix(const float* __restrict__ X,
                                                  const float* __restrict__ W)
{
    __shared__ float x_s[NI][BB];   // [n][b]
    const int t  = threadIdx.x;
    const int i0 = blockIdx.x * K1_CHUNK;

    float acc[BB][4];
#pragma unroll
    for (int b = 0; b < BB; b++)
#pragma unroll
        for (int q = 0; q < 4; q++) acc[b][q] = 0.0f;

    const float4* W4 = (const float4*)W;
    float4*       U4 = (float4*)g_U;

    for (int ci = 0; ci < K1_CHUNK; ci++) {
        const int i = i0 + ci;
        __syncthreads();
        if (t < BB * NI) {
            const int b = t >> 4, n = t & 15;
            x_s[n][b] = X[((size_t)b * CI + i) * NI + n];
        }
        __syncthreads();

#pragma unroll
        for (int ng = 0; ng < 4; ng++) {
            float4 wst[4];
#pragma unroll
            for (int k = 0; k < 4; k++)
                wst[k] = W4[(size_t)(i * NI + ng * 4 + k) * (JM / 4) + t];
#pragma unroll
            for (int k = 0; k < 4; k++) {
                const int n = ng * 4 + k;
                const float2* xs2 = (const float2*)&x_s[n][0];
                const float4  wv  = wst[k];
#pragma unroll
                for (int bp = 0; bp < 8; bp++) {
                    const float2 xp = xs2[bp];
                    acc[2*bp  ][0] += xp.x * wv.x;
                    acc[2*bp  ][1] += xp.x * wv.y;
                    acc[2*bp  ][2] += xp.x * wv.z;
                    acc[2*bp  ][3] += xp.x * wv.w;
                    acc[2*bp+1][0] += xp.y * wv.x;
                    acc[2*bp+1][1] += xp.y * wv.y;
                    acc[2*bp+1][2] += xp.y * wv.z;
                    acc[2*bp+1][3] += xp.y * wv.w;
                }
            }
        }
        // write prefix row for this i
#pragma unroll
        for (int b = 0; b < BB; b++)
            U4[(size_t)(i * BB + b) * (JM / 4) + t] =
                make_float4(acc[b][0], acc[b][1], acc[b][2], acc[b][3]);
    }
}

// ---------------------------------------------------------------------------
// K2: s0[b,jm] = sum over chunks of last prefix row.  g_s must be zero
// beforehand (guaranteed by BSS init / previous squash).
// Grid: 512 blocks x 256 threads: bid -> (cquarter, jmchunk, b)
// ---------------------------------------------------------------------------
__global__ void __launch_bounds__(256) k_s0_reduce()
{
    const int bid = blockIdx.x;
    const int cq  = bid & 3;
    const int jmc = (bid >> 2) & 7;
    const int b   = bid >> 5;
    const int jm  = jmc * 256 + threadIdx.x;
    const int c0  = cq * (K1_NBLK / 4);

    float a = 0.0f;
#pragma unroll 8
    for (int c = 0; c < K1_NBLK / 4; c++) {
        const int row = (c0 + c) * K1_CHUNK + (K1_CHUNK - 1);
        a += g_U[(size_t)(row * BB + b) * JM + jm];
    }
    atomicAdd(&g_s[b * JM + jm], a);
}

// ---------------------------------------------------------------------------
// Routing pass (pass=1 uses v0 & b_prev=0, writes b1; pass=2 uses v1 & b1).
// Grid: (32 i-chunks, 16 b), 256 threads. Thread owns jm in [8t, 8t+8):
//   j = t>>2, m-offset = (t&3)*8.  Reconstructs u_i = P[i] - P[i-1].
// Accumulates s into g_s via one atomic flush per thread.
// ---------------------------------------------------------------------------
__global__ void __launch_bounds__(256) k_route(int pass)
{
    __shared__ float v_s[JM];
    __shared__ float red_max[2][8];
    __shared__ float red_sum[2][8];

    const int t  = threadIdx.x;
    const int b  = blockIdx.y;
    const int i0 = blockIdx.x * RT_ICHUNK;
    const int j  = t >> 2;

    // load v for this b into smem
    {
        float4*       vs4 = (float4*)v_s;
        const float4* gv4 = (const float4*)g_v;
        vs4[2*t]     = gv4[b * (JM/4) + 2*t];
        vs4[2*t + 1] = gv4[b * (JM/4) + 2*t + 1];
    }
    __syncthreads();

    float s_loc[8], prev[8];
#pragma unroll
    for (int k = 0; k < 8; k++) { s_loc[k] = 0.0f; prev[k] = 0.0f; }

    const float4* U4 = (const float4*)g_U;
    float4 c0 = U4[(size_t)(i0 * BB + b) * (JM/4) + 2*t];
    float4 c1 = U4[(size_t)(i0 * BB + b) * (JM/4) + 2*t + 1];

    for (int ii = 0; ii < RT_ICHUNK; ii++) {
        const int i = i0 + ii;
        // prefetch next row
        float4 nx0 = c0, nx1 = c1;
        if (ii < RT_ICHUNK - 1) {
            nx0 = U4[(size_t)((i + 1) * BB + b) * (JM/4) + 2*t];
            nx1 = U4[(size_t)((i + 1) * BB + b) * (JM/4) + 2*t + 1];
        }

        float u[8];
        u[0]=c0.x; u[1]=c0.y; u[2]=c0.z; u[3]=c0.w;
        u[4]=c1.x; u[5]=c1.y; u[6]=c1.z; u[7]=c1.w;
        if ((i & (K1_CHUNK - 1)) != 0) {
#pragma unroll
            for (int k = 0; k < 8; k++) u[k] -= prev[k];
        }
        prev[0]=c0.x; prev[1]=c0.y; prev[2]=c0.z; prev[3]=c0.w;
        prev[4]=c1.x; prev[5]=c1.y; prev[6]=c1.z; prev[7]=c1.w;

        // agreement dot:  d = sum_m v[b,j,m] * u[b,i,j,m]
        float d = 0.0f;
#pragma unroll
        for (int k = 0; k < 8; k++) d += v_s[8*t + k] * u[k];
        d += __shfl_xor_sync(0xffffffffu, d, 1);
        d += __shfl_xor_sync(0xffffffffu, d, 2);   // all 4 lanes of j hold full dot

        float bl = d;
        if (pass == 2) {
            bl += g_bl[((size_t)b * CI + i) * CJ + j];
        } else {
            if ((t & 3) == 0) g_bl[((size_t)b * CI + i) * CJ + j] = bl;
        }

        // softmax over j (64 values, 4 redundant copies each), alpha = 8
        const float z  = bl * 8.0f;
        float wm = z;
#pragma unroll
        for (int o = 16; o > 0; o >>= 1)
            wm = fmaxf(wm, __shfl_xor_sync(0xffffffffu, wm, o));
        const int wp = t >> 5;
        const int pb = ii & 1;
        if ((t & 31) == 0) red_max[pb][wp] = wm;
        __syncthreads();
        float mx = red_max[pb][0];
#pragma unroll
        for (int k = 1; k < 8; k++) mx = fmaxf(mx, red_max[pb][k]);

        const float e  = exp2f((z - mx) * 1.44269504f);
        float es = ((t & 3) == 0) ? e : 0.0f;
#pragma unroll
        for (int o = 16; o > 0; o >>= 1)
            es += __shfl_xor_sync(0xffffffffu, es, o);
        if ((t & 31) == 0) red_sum[pb][wp] = es;
        __syncthreads();
        float tot = red_sum[pb][0];
#pragma unroll
        for (int k = 1; k < 8; k++) tot += red_sum[pb][k];

        const float cc = 64.0f * e / tot;   // softmax * CH_J
#pragma unroll
        for (int k = 0; k < 8; k++) s_loc[k] += cc * u[k];

        c0 = nx0; c1 = nx1;
    }

#pragma unroll
    for (int k = 0; k < 8; k++)
        atomicAdd(&g_s[b * JM + 8*t + k], s_loc[k]);
}

// ---------------------------------------------------------------------------
// Squash: v = (|s|^2/(1+|s|^2)) * s * rsqrt(|s|^2 + eps) per (b,j).
// Also re-zeroes g_s so the next pass / next graph replay starts clean.
// dst == nullptr -> write g_v, else write dst (final output).
// Grid: 64 blocks x 512 threads (warp per (b,j)).
// ---------------------------------------------------------------------------
__global__ void __launch_bounds__(512) k_squash(float* dst)
{
    const int t    = threadIdx.x;
    const int gw   = blockIdx.x * 16 + (t >> 5);
    const int lane = t & 31;
    const int b    = gw >> 6;
    const int j    = gw & 63;
    const int idx  = b * JM + j * NJ + lane;

    const float s = g_s[idx];
    float sq = s * s;
#pragma unroll
    for (int o = 16; o > 0; o >>= 1)
        sq += __shfl_xor_sync(0xffffffffu, sq, o);

    const float coef = (sq / (1.0f + sq)) * rsqrtf(sq + 1e-7f);
    float* out = dst ? dst : g_v;
    out[idx] = s * coef;
    g_s[idx] = 0.0f;
}

// ---------------------------------------------------------------------------
extern "C" void kernel_launch(void* const* d_in, const int* in_sizes, int n_in,
                              void* d_out, int out_size)
{
    const float* X = (const float*)d_in[0];
    const float* W = (const float*)d_in[1];
    if (n_in >= 2 && in_sizes[0] > in_sizes[1]) {   // defensive order check
        const float* tmp = X; X = W; W = tmp;
    }
    float* out = (float*)d_out;

    // u (as chunk-local prefix sums) + fused data for s0
    k_u_prefix<<<K1_NBLK, 512>>>(X, W);
    // r=0: s0 = sum_i u  (from chunk-last rows; g_s is zero here)
    k_s0_reduce<<<512, 256>>>();
    k_squash<<<64, 512>>>(nullptr);                 // v0, zero g_s
    // r=1: b1 = <v0,u>; c = softmax(8*b1)*64; s1 = sum_i c*u
    k_route<<<dim3(RT_NIB, BB), 256>>>(1);
    k_squash<<<64, 512>>>(nullptr);                 // v1, zero g_s
    // r=2: b2 = b1 + <v1,u>; c = softmax(8*b2)*64; s2 = sum_i c*u
    k_route<<<dim3(RT_NIB, BB), 256>>>(2);
    k_squash<<<64, 512>>>(out);                     // v2 -> output, zero g_s
    (void)out_size;
}

// round 3
// speedup vs baseline: 1.0958x; 1.0958x over previous
#include <cuda_runtime.h>
#include <math.h>

// Problem constants
#define BB   16      // batch
#define CI   2048    // input capsules
#define NI   16      // input capsule dim
#define CJ   64      // output capsules
#define NJ   32      // output capsule dim
#define JM   2048    // CJ*NJ
#define K1_CHUNK 4   // i's per K1 block (prefix-sum chunk length)
#define K1_NBLK  (CI / K1_CHUNK)          // 512
#define RT_ICHUNK 64                      // i's per routing block (multiple of K1_CHUNK)
#define RT_NIB    (CI / RT_ICHUNK)        // 32

// Scratch in device globals (allocation-free kernel_launch).
// g_U holds chunk-local PREFIX sums of u over i within each K1 chunk:
//   for i with i%4==c, P[i] = sum_{i' in [i-c, i]} u[i']   (layout [i][b][jm])
static __device__ float g_U[(size_t)CI * BB * JM];   // 268 MB
static __device__ float g_s[BB * JM];                // s accumulator (BSS zero at start)
static __device__ float g_v[BB * JM];                // squashed v
static __device__ float g_bl[(size_t)BB * CI * CJ];  // routing logits b  [b][i][j]

// ---------------------------------------------------------------------------
// K1: compute u[b,i,jm] = sum_n x[b,i,n] * w[i,n,jm]; write chunk-local
// prefix sums over i (never reset acc within the 4-i chunk).
// ---------------------------------------------------------------------------
__global__ void __launch_bounds__(512) k_u_prefix(const float* __restrict__ X,
                                                  const float* __restrict__ W)
{
    __shared__ float x_s[NI][BB];   // [n][b]
    const int t  = threadIdx.x;
    const int i0 = blockIdx.x * K1_CHUNK;

    float acc[BB][4];
#pragma unroll
    for (int b = 0; b < BB; b++)
#pragma unroll
        for (int q = 0; q < 4; q++) acc[b][q] = 0.0f;

    const float4* W4 = (const float4*)W;
    float4*       U4 = (float4*)g_U;

    for (int ci = 0; ci < K1_CHUNK; ci++) {
        const int i = i0 + ci;
        __syncthreads();
        if (t < BB * NI) {
            const int b = t >> 4, n = t & 15;
            x_s[n][b] = X[((size_t)b * CI + i) * NI + n];
        }
        __syncthreads();

#pragma unroll
        for (int ng = 0; ng < 4; ng++) {
            float4 wst[4];
#pragma unroll
            for (int k = 0; k < 4; k++)
                wst[k] = W4[(size_t)(i * NI + ng * 4 + k) * (JM / 4) + t];
#pragma unroll
            for (int k = 0; k < 4; k++) {
                const int n = ng * 4 + k;
                const float2* xs2 = (const float2*)&x_s[n][0];
                const float4  wv  = wst[k];
#pragma unroll
                for (int bp = 0; bp < 8; bp++) {
                    const float2 xp = xs2[bp];
                    acc[2*bp  ][0] += xp.x * wv.x;
                    acc[2*bp  ][1] += xp.x * wv.y;
                    acc[2*bp  ][2] += xp.x * wv.z;
                    acc[2*bp  ][3] += xp.x * wv.w;
                    acc[2*bp+1][0] += xp.y * wv.x;
                    acc[2*bp+1][1] += xp.y * wv.y;
                    acc[2*bp+1][2] += xp.y * wv.z;
                    acc[2*bp+1][3] += xp.y * wv.w;
                }
            }
        }
#pragma unroll
        for (int b = 0; b < BB; b++)
            U4[(size_t)(i * BB + b) * (JM / 4) + t] =
                make_float4(acc[b][0], acc[b][1], acc[b][2], acc[b][3]);
    }
}

// ---------------------------------------------------------------------------
// K2: s0[b,jm] = sum over chunks of last prefix row. g_s zero beforehand.
// ---------------------------------------------------------------------------
__global__ void __launch_bounds__(256) k_s0_reduce()
{
    const int bid = blockIdx.x;
    const int cq  = bid & 3;
    const int jmc = (bid >> 2) & 7;
    const int b   = bid >> 5;
    const int jm  = jmc * 256 + threadIdx.x;
    const int c0  = cq * (K1_NBLK / 4);

    float a = 0.0f;
#pragma unroll 8
    for (int c = 0; c < K1_NBLK / 4; c++) {
        const int row = (c0 + c) * K1_CHUNK + (K1_CHUNK - 1);
        a += g_U[(size_t)(row * BB + b) * JM + jm];
    }
    atomicAdd(&g_s[b * JM + jm], a);
}

// ---------------------------------------------------------------------------
// Routing pass (pass=1 uses v0 & b_prev=0, writes b1; pass=2 uses v1 & b1).
// Grid: (32 i-chunks, 16 b), 256 threads. Thread owns jm in [8t, 8t+8):
//   j = t>>2, m-offset = (t&3)*8.  Reconstructs u_i from chunk-local prefixes.
//
// Optimizations vs v1:
//  - no max-subtraction in softmax (logits provably bounded, fp32-safe, exact)
//  - v held in registers (no in-loop LDS)
//  - 2 i's per barrier (double-buffered smem reduce), 3-shfl warp reductions
// ---------------------------------------------------------------------------
__global__ void __launch_bounds__(256, 3) k_route(int pass)
{
    __shared__ float red_sum[2][2][8];   // [buf][which-i][warp]

    const int t  = threadIdx.x;
    const int l  = t & 31;
    const int wp = t >> 5;
    const int gl = t & 3;
    const int b  = blockIdx.y;
    const int i0 = blockIdx.x * RT_ICHUNK;
    const int j  = t >> 2;

    // v for this b: thread reuses the same 8 values all 64 iterations
    float v_r[8];
    {
        const float4* gv4 = (const float4*)g_v;
        float4 va = gv4[b * (JM/4) + 2*t];
        float4 vb = gv4[b * (JM/4) + 2*t + 1];
        v_r[0]=va.x; v_r[1]=va.y; v_r[2]=va.z; v_r[3]=va.w;
        v_r[4]=vb.x; v_r[5]=vb.y; v_r[6]=vb.z; v_r[7]=vb.w;
    }

    float s_loc[8], prev[8];
#pragma unroll
    for (int k = 0; k < 8; k++) { s_loc[k] = 0.0f; prev[k] = 0.0f; }

    const float4* U4 = (const float4*)g_U;
    const size_t rstride = (size_t)BB * (JM/4);          // float4 units per i-row
    const size_t base    = ((size_t)i0 * BB + b) * (JM/4) + 2*t;

    float* BL = g_bl + ((size_t)b * CI + i0) * CJ + j;

    float4 A0 = U4[base],           A1 = U4[base + 1];
    float4 B0 = U4[base + rstride], B1 = U4[base + rstride + 1];

#pragma unroll 4
    for (int bi = 0; bi < RT_ICHUNK / 2; bi++) {
        const int i = i0 + 2 * bi;

        // prefetch next pair of rows
        float4 C0, C1, D0, D1;
        if (bi < RT_ICHUNK / 2 - 1) {
            const size_t nb = base + (size_t)(2*bi + 2) * rstride;
            C0 = U4[nb];           C1 = U4[nb + 1];
            D0 = U4[nb + rstride]; D1 = U4[nb + rstride + 1];
        } else { C0 = A0; C1 = A1; D0 = B0; D1 = B1; }

        // previous logits (pass 2) — issue early to hide latency
        float blpA = 0.0f, blpB = 0.0f;
        if (pass == 2) {
            blpA = BL[(size_t)(2*bi)     * CJ];
            blpB = BL[(size_t)(2*bi + 1) * CJ];
        }

        float A[8]  = {A0.x,A0.y,A0.z,A0.w,A1.x,A1.y,A1.z,A1.w};
        float Bv[8] = {B0.x,B0.y,B0.z,B0.w,B1.x,B1.y,B1.z,B1.w};

        // reconstruct u from chunk-local prefixes (chunk = 4, batch = 2)
        if ((i & 3) == 0) {
#pragma unroll
            for (int k = 0; k < 8; k++) { Bv[k] -= A[k]; prev[k] = A[k] + Bv[k]; }
        } else {
#pragma unroll
            for (int k = 0; k < 8; k++) { Bv[k] -= A[k]; A[k] -= prev[k]; }
        }

        // agreement dots  d = sum_m v[j,m] u[i,j,m]
        float dA = 0.0f, dB = 0.0f;
#pragma unroll
        for (int k = 0; k < 8; k++) { dA += v_r[k]*A[k]; dB += v_r[k]*Bv[k]; }
        dA += __shfl_xor_sync(0xffffffffu, dA, 1);
        dA += __shfl_xor_sync(0xffffffffu, dA, 2);
        dB += __shfl_xor_sync(0xffffffffu, dB, 1);
        dB += __shfl_xor_sync(0xffffffffu, dB, 2);

        if (pass == 2) { dA += blpA; dB += blpB; }
        else if (gl == 0) {
            BL[(size_t)(2*bi)     * CJ] = dA;
            BL[(size_t)(2*bi + 1) * CJ] = dB;
        }

        // softmax over j, alpha=8, no max shift (|8b| <~ 20, fp32-safe, exact)
        const float eA = exp2f(dA * 11.541560327111707f);   // 8*log2(e)
        const float eB = exp2f(dB * 11.541560327111707f);

        // warp partial sums over this warp's 8 distinct j (lanes mod 4 identical)
        float esA = eA, esB = eB;
#pragma unroll
        for (int o = 4; o <= 16; o <<= 1) {
            esA += __shfl_xor_sync(0xffffffffu, esA, o);
            esB += __shfl_xor_sync(0xffffffffu, esB, o);
        }
        const int pb = bi & 1;
        if (l == 0) { red_sum[pb][0][wp] = esA; red_sum[pb][1][wp] = esB; }
        __syncthreads();
        float totA = red_sum[pb][0][0], totB = red_sum[pb][1][0];
#pragma unroll
        for (int k = 1; k < 8; k++) { totA += red_sum[pb][0][k]; totB += red_sum[pb][1][k]; }

        const float ccA = __fdividef(64.0f * eA, totA);
        const float ccB = __fdividef(64.0f * eB, totB);
#pragma unroll
        for (int k = 0; k < 8; k++) s_loc[k] += ccA * A[k] + ccB * Bv[k];

        A0 = C0; A1 = C1; B0 = D0; B1 = D1;
    }

#pragma unroll
    for (int k = 0; k < 8; k++)
        atomicAdd(&g_s[b * JM + 8*t + k], s_loc[k]);
}

// ---------------------------------------------------------------------------
// Squash: v = (|s|^2/(1+|s|^2)) * s * rsqrt(|s|^2 + eps). Re-zeroes g_s.
// ---------------------------------------------------------------------------
__global__ void __launch_bounds__(512) k_squash(float* dst)
{
    const int t    = threadIdx.x;
    const int gw   = blockIdx.x * 16 + (t >> 5);
    const int lane = t & 31;
    const int b    = gw >> 6;
    const int j    = gw & 63;
    const int idx  = b * JM + j * NJ + lane;

    const float s = g_s[idx];
    float sq = s * s;
#pragma unroll
    for (int o = 16; o > 0; o >>= 1)
        sq += __shfl_xor_sync(0xffffffffu, sq, o);

    const float coef = (sq / (1.0f + sq)) * rsqrtf(sq + 1e-7f);
    float* out = dst ? dst : g_v;
    out[idx] = s * coef;
    g_s[idx] = 0.0f;
}

// ---------------------------------------------------------------------------
extern "C" void kernel_launch(void* const* d_in, const int* in_sizes, int n_in,
                              void* d_out, int out_size)
{
    const float* X = (const float*)d_in[0];
    const float* W = (const float*)d_in[1];
    if (n_in >= 2 && in_sizes[0] > in_sizes[1]) {   // defensive order check
        const float* tmp = X; X = W; W = tmp;
    }
    float* out = (float*)d_out;

    k_u_prefix<<<K1_NBLK, 512>>>(X, W);
    k_s0_reduce<<<512, 256>>>();
    k_squash<<<64, 512>>>(nullptr);                 // v0, zero g_s
    k_route<<<dim3(RT_NIB, BB), 256>>>(1);
    k_squash<<<64, 512>>>(nullptr);                 // v1, zero g_s
    k_route<<<dim3(RT_NIB, BB), 256>>>(2);
    k_squash<<<64, 512>>>(out);                     // v2 -> output, zero g_s
    (void)out_size;
}

// round 4
// speedup vs baseline: 1.2188x; 1.1122x over previous
#include <cuda_runtime.h>
#include <math.h>

// Problem constants
#define BB   16      // batch
#define CI   2048    // input capsules
#define NI   16      // input capsule dim
#define CJ   64      // output capsules
#define NJ   32      // output capsule dim
#define JM   2048    // CJ*NJ
#define K1_CHUNK 4   // i's per K1 block (prefix-sum chunk length)
#define K1_NBLK  (CI / K1_CHUNK)          // 512
#define RT_ICHUNK 32                      // i's per routing block (multiple of 4)
#define RT_NIB    (CI / RT_ICHUNK)        // 64

// Scratch in device globals (allocation-free kernel_launch).
// g_U holds chunk-local PREFIX sums of u over i within each K1 chunk:
//   for i with i%4==c, P[i] = sum_{i' in [i-c, i]} u[i']   (layout [i][b][jm])
static __device__ float g_U[(size_t)CI * BB * JM];   // 268 MB
static __device__ float g_s[BB * JM];                // s accumulator (BSS zero at start)
static __device__ float g_v[BB * JM];                // squashed v
static __device__ float g_bl[(size_t)BB * CI * CJ];  // routing logits b  [b][i][j]

// ---------------------------------------------------------------------------
// K1: compute u[b,i,jm] = sum_n x[b,i,n] * w[i,n,jm]; write chunk-local
// prefix sums over i (never reset acc within the 4-i chunk).
// ---------------------------------------------------------------------------
__global__ void __launch_bounds__(512) k_u_prefix(const float* __restrict__ X,
                                                  const float* __restrict__ W)
{
    __shared__ float x_s[NI][BB];   // [n][b]
    const int t  = threadIdx.x;
    const int i0 = blockIdx.x * K1_CHUNK;

    float acc[BB][4];
#pragma unroll
    for (int b = 0; b < BB; b++)
#pragma unroll
        for (int q = 0; q < 4; q++) acc[b][q] = 0.0f;

    const float4* W4 = (const float4*)W;
    float4*       U4 = (float4*)g_U;

    for (int ci = 0; ci < K1_CHUNK; ci++) {
        const int i = i0 + ci;
        __syncthreads();
        if (t < BB * NI) {
            const int b = t >> 4, n = t & 15;
            x_s[n][b] = X[((size_t)b * CI + i) * NI + n];
        }
        __syncthreads();

#pragma unroll
        for (int ng = 0; ng < 4; ng++) {
            float4 wst[4];
#pragma unroll
            for (int k = 0; k < 4; k++)
                wst[k] = W4[(size_t)(i * NI + ng * 4 + k) * (JM / 4) + t];
#pragma unroll
            for (int k = 0; k < 4; k++) {
                const int n = ng * 4 + k;
                const float2* xs2 = (const float2*)&x_s[n][0];
                const float4  wv  = wst[k];
#pragma unroll
                for (int bp = 0; bp < 8; bp++) {
                    const float2 xp = xs2[bp];
                    acc[2*bp  ][0] += xp.x * wv.x;
                    acc[2*bp  ][1] += xp.x * wv.y;
                    acc[2*bp  ][2] += xp.x * wv.z;
                    acc[2*bp  ][3] += xp.x * wv.w;
                    acc[2*bp+1][0] += xp.y * wv.x;
                    acc[2*bp+1][1] += xp.y * wv.y;
                    acc[2*bp+1][2] += xp.y * wv.z;
                    acc[2*bp+1][3] += xp.y * wv.w;
                }
            }
        }
#pragma unroll
        for (int b = 0; b < BB; b++)
            U4[(size_t)(i * BB + b) * (JM / 4) + t] =
                make_float4(acc[b][0], acc[b][1], acc[b][2], acc[b][3]);
    }
}

// ---------------------------------------------------------------------------
// K2: s0[b,jm] = sum over chunks of last prefix row. g_s zero beforehand.
// ---------------------------------------------------------------------------
__global__ void __launch_bounds__(256) k_s0_reduce()
{
    const int bid = blockIdx.x;
    const int cq  = bid & 3;
    const int jmc = (bid >> 2) & 7;
    const int b   = bid >> 5;
    const int jm  = jmc * 256 + threadIdx.x;
    const int c0  = cq * (K1_NBLK / 4);

    float a = 0.0f;
#pragma unroll 8
    for (int c = 0; c < K1_NBLK / 4; c++) {
        const int row = (c0 + c) * K1_CHUNK + (K1_CHUNK - 1);
        a += g_U[(size_t)(row * BB + b) * JM + jm];
    }
    atomicAdd(&g_s[b * JM + jm], a);
}

// ---------------------------------------------------------------------------
// Routing pass (pass=1 uses v0 & b_prev=0, writes b1; pass=2 uses v1 & b1).
// Grid: (64 i-chunks, 16 b), 256 threads. Thread owns jm in [8t, 8t+8):
//   j = t>>2, m-offset = (t&3)*8.
//
// v3: 4 i's (one full prefix chunk) per barrier -> 8 barriers per block,
// batch-local diff reconstruction (no carried prev), 4 independent softmax
// chains for ILP, float4 broadcast reads of the cross-warp sums, and a 4x
// larger grid (1024 blocks) so occupancy is warp-limited, not grid-limited.
// ---------------------------------------------------------------------------
__global__ void __launch_bounds__(256) k_route(int pass)
{
    __shared__ float red_sum[2][4][8];   // [buf][which-i][warp]

    const int t  = threadIdx.x;
    const int l  = t & 31;
    const int wp = t >> 5;
    const int gl = t & 3;
    const int b  = blockIdx.y;
    const int i0 = blockIdx.x * RT_ICHUNK;
    const int j  = t >> 2;

    // v for this b: thread reuses the same 8 values every iteration
    float v_r[8];
    {
        const float4* gv4 = (const float4*)g_v;
        float4 va = gv4[b * (JM/4) + 2*t];
        float4 vb = gv4[b * (JM/4) + 2*t + 1];
        v_r[0]=va.x; v_r[1]=va.y; v_r[2]=va.z; v_r[3]=va.w;
        v_r[4]=vb.x; v_r[5]=vb.y; v_r[6]=vb.z; v_r[7]=vb.w;
    }

    float s_loc[8];
#pragma unroll
    for (int k = 0; k < 8; k++) s_loc[k] = 0.0f;

    const float4* U4 = (const float4*)g_U;
    const size_t rstride = (size_t)BB * (JM/4);          // float4 units per i-row
    const size_t base    = ((size_t)i0 * BB + b) * (JM/4) + 2*t;

    float* BL = g_bl + ((size_t)b * CI + i0) * CJ + j;

    // load first batch of 4 prefix rows
    float4 R[4][2];
#pragma unroll
    for (int r = 0; r < 4; r++) {
        R[r][0] = U4[base + (size_t)r * rstride];
        R[r][1] = U4[base + (size_t)r * rstride + 1];
    }

    for (int bi = 0; bi < RT_ICHUNK / 4; bi++) {
        // prefetch next batch
        float4 Nx[4][2];
        if (bi < RT_ICHUNK / 4 - 1) {
            const size_t nb = base + (size_t)(4*bi + 4) * rstride;
#pragma unroll
            for (int r = 0; r < 4; r++) {
                Nx[r][0] = U4[nb + (size_t)r * rstride];
                Nx[r][1] = U4[nb + (size_t)r * rstride + 1];
            }
        }

        // previous logits (pass 2) — issue early
        float blp[4];
        if (pass == 2) {
#pragma unroll
            for (int r = 0; r < 4; r++)
                blp[r] = BL[(size_t)(4*bi + r) * CJ];
        }

        // unpack and reconstruct u from prefix rows (batch == prefix chunk)
        float u[4][8];
#pragma unroll
        for (int r = 0; r < 4; r++) {
            u[r][0]=R[r][0].x; u[r][1]=R[r][0].y; u[r][2]=R[r][0].z; u[r][3]=R[r][0].w;
            u[r][4]=R[r][1].x; u[r][5]=R[r][1].y; u[r][6]=R[r][1].z; u[r][7]=R[r][1].w;
        }
#pragma unroll
        for (int k = 0; k < 8; k++) {
            u[3][k] -= u[2][k];
            u[2][k] -= u[1][k];
            u[1][k] -= u[0][k];
        }

        // agreement dots d[r] = sum_m v[j,m] u[i_r,j,m]  (4 independent chains)
        float d[4] = {0.0f, 0.0f, 0.0f, 0.0f};
#pragma unroll
        for (int k = 0; k < 8; k++) {
#pragma unroll
            for (int r = 0; r < 4; r++) d[r] += v_r[k] * u[r][k];
        }
#pragma unroll
        for (int r = 0; r < 4; r++) {
            d[r] += __shfl_xor_sync(0xffffffffu, d[r], 1);
            d[r] += __shfl_xor_sync(0xffffffffu, d[r], 2);
        }

        if (pass == 2) {
#pragma unroll
            for (int r = 0; r < 4; r++) d[r] += blp[r];
        } else if (gl == 0) {
#pragma unroll
            for (int r = 0; r < 4; r++)
                BL[(size_t)(4*bi + r) * CJ] = d[r];
        }

        // softmax over j, alpha=8, no max shift (|8b| bounded, fp32-safe, exact)
        float e[4], es[4];
#pragma unroll
        for (int r = 0; r < 4; r++) {
            e[r]  = exp2f(d[r] * 11.541560327111707f);   // 8*log2(e)
            es[r] = e[r];
        }
#pragma unroll
        for (int o = 4; o <= 16; o <<= 1) {
#pragma unroll
            for (int r = 0; r < 4; r++)
                es[r] += __shfl_xor_sync(0xffffffffu, es[r], o);
        }
        const int pb = bi & 1;
        if (l == 0) {
#pragma unroll
            for (int r = 0; r < 4; r++) red_sum[pb][r][wp] = es[r];
        }
        __syncthreads();

        const float4* rs = (const float4*)&red_sum[pb][0][0];
        float tot[4];
#pragma unroll
        for (int r = 0; r < 4; r++) {
            const float4 a = rs[2*r], c = rs[2*r + 1];
            tot[r] = ((a.x + a.y) + (a.z + a.w)) + ((c.x + c.y) + (c.z + c.w));
        }

#pragma unroll
        for (int r = 0; r < 4; r++) {
            const float cc = __fdividef(64.0f * e[r], tot[r]);
#pragma unroll
            for (int k = 0; k < 8; k++) s_loc[k] += cc * u[r][k];
        }

#pragma unroll
        for (int r = 0; r < 4; r++) { R[r][0] = Nx[r][0]; R[r][1] = Nx[r][1]; }
    }

#pragma unroll
    for (int k = 0; k < 8; k++)
        atomicAdd(&g_s[b * JM + 8*t + k], s_loc[k]);
}

// ---------------------------------------------------------------------------
// Squash: v = (|s|^2/(1+|s|^2)) * s * rsqrt(|s|^2 + eps). Re-zeroes g_s.
// ---------------------------------------------------------------------------
__global__ void __launch_bounds__(512) k_squash(float* dst)
{
    const int t    = threadIdx.x;
    const int gw   = blockIdx.x * 16 + (t >> 5);
    const int lane = t & 31;
    const int b    = gw >> 6;
    const int j    = gw & 63;
    const int idx  = b * JM + j * NJ + lane;

    const float s = g_s[idx];
    float sq = s * s;
#pragma unroll
    for (int o = 16; o > 0; o >>= 1)
        sq += __shfl_xor_sync(0xffffffffu, sq, o);

    const float coef = (sq / (1.0f + sq)) * rsqrtf(sq + 1e-7f);
    float* out = dst ? dst : g_v;
    out[idx] = s * coef;
    g_s[idx] = 0.0f;
}

// ---------------------------------------------------------------------------
extern "C" void kernel_launch(void* const* d_in, const int* in_sizes, int n_in,
                              void* d_out, int out_size)
{
    const float* X = (const float*)d_in[0];
    const float* W = (const float*)d_in[1];
    if (n_in >= 2 && in_sizes[0] > in_sizes[1]) {   // defensive order check
        const float* tmp = X; X = W; W = tmp;
    }
    float* out = (float*)d_out;

    k_u_prefix<<<K1_NBLK, 512>>>(X, W);
    k_s0_reduce<<<512, 256>>>();
    k_squash<<<64, 512>>>(nullptr);                 // v0, zero g_s
    k_route<<<dim3(RT_NIB, BB), 256>>>(1);
    k_squash<<<64, 512>>>(nullptr);                 // v1, zero g_s
    k_route<<<dim3(RT_NIB, BB), 256>>>(2);
    k_squash<<<64, 512>>>(out);                     // v2 -> output, zero g_s
    (void)out_size;
}

// round 5
// speedup vs baseline: 1.3110x; 1.0756x over previous
#include <cuda_runtime.h>
#include <cuda_fp16.h>
#include <math.h>

// Problem constants
#define BB   16      // batch
#define CI   2048    // input capsules
#define NI   16      // input capsule dim
#define CJ   64      // output capsules
#define NJ   32      // output capsule dim
#define JM   2048    // CJ*NJ
#define K1_CHUNK 2   // i's per prefix chunk (acc reset period)
#define K1_IBLK  4   // i's per K1 block
#define K1_NBLK  (CI / K1_IBLK)           // 512
#define RT_ICHUNK 32                      // i's per routing block (even)
#define RT_NIB    (CI / RT_ICHUNK)        // 64

typedef unsigned long long ull;

// Scratch (allocation-free kernel_launch). g_Uh holds chunk-local PREFIX sums
// of u over i within each 2-i chunk, fp16: even i: P=u_i; odd i: P=u_{i-1}+u_i.
// Layout [i][b][jm].
static __device__ __half g_Uh[(size_t)CI * BB * JM];  // 134 MB
static __device__ float  g_s[BB * JM];                // s accumulator (BSS zero)
static __device__ float  g_v[BB * JM];                // squashed v
static __device__ float  g_bl[(size_t)BB * CI * CJ];  // routing logits [b][i][j]

// ---- packed fp32 pair helpers (fma.rn.f32x2, sm_100+) ----------------------
__device__ __forceinline__ void fma2(ull& d, ull a, ull b) {
    asm("fma.rn.f32x2 %0, %1, %2, %0;" : "+l"(d) : "l"(a), "l"(b));
}
__device__ __forceinline__ ull pack2(float x, float y) {
    ull r; asm("mov.b64 %0, {%1, %2};" : "=l"(r) : "f"(x), "f"(y)); return r;
}
__device__ __forceinline__ float2 unpack2(ull v) {
    float2 r; asm("mov.b64 {%0, %1}, %2;" : "=f"(r.x), "=f"(r.y) : "l"(v)); return r;
}

// ---------------------------------------------------------------------------
// K1: u[b,i,jm] = sum_n x[b,i,n] * w[i,n,jm]; writes 2-i chunk prefix sums as
// fp16. 512 blocks x 512 threads; thread owns jm quad [4t,4t+4).
// Inner product uses fma.rn.f32x2 over batch pairs (x pairs direct from smem).
// ---------------------------------------------------------------------------
__global__ void __launch_bounds__(512) k_u_prefix(const float* __restrict__ X,
                                                  const float* __restrict__ W)
{
    __shared__ __align__(16) float x_s[NI][BB];   // [n][b]
    const int t  = threadIdx.x;
    const int i0 = blockIdx.x * K1_IBLK;

    ull acc2[8][4];   // [b-pair][q]: packed (acc[2bp][q], acc[2bp+1][q])

    const float4* W4 = (const float4*)W;
    uint2*        U2 = (uint2*)g_Uh;              // 4 halfs per uint2

    for (int ci = 0; ci < K1_IBLK; ci++) {
        const int i = i0 + ci;
        if ((ci & (K1_CHUNK - 1)) == 0) {
#pragma unroll
            for (int bp = 0; bp < 8; bp++)
#pragma unroll
                for (int q = 0; q < 4; q++) acc2[bp][q] = 0ull;
        }
        __syncthreads();
        if (t < BB * NI) {
            const int b = t >> 4, n = t & 15;
            x_s[n][b] = X[((size_t)b * CI + i) * NI + n];
        }
        __syncthreads();

#pragma unroll
        for (int ng = 0; ng < 4; ng++) {
            float4 wst[4];
#pragma unroll
            for (int k = 0; k < 4; k++)
                wst[k] = W4[(size_t)(i * NI + ng * 4 + k) * (JM / 4) + t];
#pragma unroll
            for (int k = 0; k < 4; k++) {
                const int n = ng * 4 + k;
                const ull* xs8 = (const ull*)&x_s[n][0];   // batch pairs
                const float4 wv = wst[k];
                const ull wd0 = pack2(wv.x, wv.x);
                const ull wd1 = pack2(wv.y, wv.y);
                const ull wd2 = pack2(wv.z, wv.z);
                const ull wd3 = pack2(wv.w, wv.w);
#pragma unroll
                for (int bp = 0; bp < 8; bp++) {
                    const ull xp = xs8[bp];
                    fma2(acc2[bp][0], xp, wd0);
                    fma2(acc2[bp][1], xp, wd1);
                    fma2(acc2[bp][2], xp, wd2);
                    fma2(acc2[bp][3], xp, wd3);
                }
            }
        }

        // store fp16 prefix row for this i (transpose b-pairs -> per-b quads)
#pragma unroll
        for (int bp = 0; bp < 8; bp++) {
            const float2 a0 = unpack2(acc2[bp][0]);
            const float2 a1 = unpack2(acc2[bp][1]);
            const float2 a2 = unpack2(acc2[bp][2]);
            const float2 a3 = unpack2(acc2[bp][3]);
            __half2 lo0 = __floats2half2_rn(a0.x, a1.x);
            __half2 lo1 = __floats2half2_rn(a2.x, a3.x);
            __half2 hi0 = __floats2half2_rn(a0.y, a1.y);
            __half2 hi1 = __floats2half2_rn(a2.y, a3.y);
            uint2 vlo, vhi;
            vlo.x = *(unsigned*)&lo0; vlo.y = *(unsigned*)&lo1;
            vhi.x = *(unsigned*)&hi0; vhi.y = *(unsigned*)&hi1;
            U2[(size_t)(i * BB + 2*bp)     * (JM/4) + t] = vlo;
            U2[(size_t)(i * BB + 2*bp + 1) * (JM/4) + t] = vhi;
        }
    }
}

// ---------------------------------------------------------------------------
// K2: s0[b,jm] = sum over odd-i prefix rows (chunk=2). g_s zero beforehand.
// Grid 512 x 256: bid -> (cq, jm-chunk, b); each sums 256 odd rows.
// ---------------------------------------------------------------------------
__global__ void __launch_bounds__(256) k_s0_reduce()
{
    const int bid = blockIdx.x;
    const int cq  = bid & 3;
    const int jmc = (bid >> 2) & 7;
    const int b   = bid >> 5;
    const int jm  = jmc * 256 + threadIdx.x;
    const int c0  = cq * (CI / 2 / 4);     // 256 odd rows per quarter

    float a = 0.0f;
#pragma unroll 8
    for (int c = 0; c < CI / 2 / 4; c++) {
        const int i = (c0 + c) * 2 + 1;    // odd i = chunk-last row
        a += __half2float(g_Uh[(size_t)(i * BB + b) * JM + jm]);
    }
    atomicAdd(&g_s[b * JM + jm], a);
}

// ---------------------------------------------------------------------------
// Routing pass (pass=1: b1=<v0,u>, writes b1; pass=2: uses v1, b1).
// Grid (64, 16) x 256 threads; thread owns jm [8t, 8t+8) (one uint4 of halfs
// per row), j = t>>2. 2-row batches == prefix chunk: uA=P0, uB=P1-P0.
// ---------------------------------------------------------------------------
__global__ void __launch_bounds__(256) k_route(int pass)
{
    __shared__ float red_sum[2][2][8];   // [buf][row][warp]

    const int t  = threadIdx.x;
    const int l  = t & 31;
    const int wp = t >> 5;
    const int gl = t & 3;
    const int b  = blockIdx.y;
    const int i0 = blockIdx.x * RT_ICHUNK;
    const int j  = t >> 2;

    float v_r[8];
    {
        const float4* gv4 = (const float4*)g_v;
        float4 va = gv4[b * (JM/4) + 2*t];
        float4 vb = gv4[b * (JM/4) + 2*t + 1];
        v_r[0]=va.x; v_r[1]=va.y; v_r[2]=va.z; v_r[3]=va.w;
        v_r[4]=vb.x; v_r[5]=vb.y; v_r[6]=vb.z; v_r[7]=vb.w;
    }

    float s_loc[8];
#pragma unroll
    for (int k = 0; k < 8; k++) s_loc[k] = 0.0f;

    const uint4* U4 = (const uint4*)g_Uh;            // 8 halfs per uint4
    const size_t rstride = (size_t)BB * (JM/8);      // uint4 per i step
    const size_t base    = ((size_t)i0 * BB + b) * (JM/8) + t;

    float* BL = g_bl + ((size_t)b * CI + i0) * CJ + j;

    uint4 A = U4[base];
    uint4 B = U4[base + rstride];

    for (int bi = 0; bi < RT_ICHUNK / 2; bi++) {
        // prefetch next chunk
        uint4 C, D;
        if (bi < RT_ICHUNK / 2 - 1) {
            const size_t nb = base + (size_t)(2*bi + 2) * rstride;
            C = U4[nb]; D = U4[nb + rstride];
        }

        float blpA = 0.0f, blpB = 0.0f;
        if (pass == 2) {
            blpA = BL[(size_t)(2*bi)     * CJ];
            blpB = BL[(size_t)(2*bi + 1) * CJ];
        }

        // convert to fp32
        float uA[8], uB[8];
        {
            float2 f;
            f = __half22float2(*(__half2*)&A.x); uA[0]=f.x; uA[1]=f.y;
            f = __half22float2(*(__half2*)&A.y); uA[2]=f.x; uA[3]=f.y;
            f = __half22float2(*(__half2*)&A.z); uA[4]=f.x; uA[5]=f.y;
            f = __half22float2(*(__half2*)&A.w); uA[6]=f.x; uA[7]=f.y;
            f = __half22float2(*(__half2*)&B.x); uB[0]=f.x; uB[1]=f.y;
            f = __half22float2(*(__half2*)&B.y); uB[2]=f.x; uB[3]=f.y;
            f = __half22float2(*(__half2*)&B.z); uB[4]=f.x; uB[5]=f.y;
            f = __half22float2(*(__half2*)&B.w); uB[6]=f.x; uB[7]=f.y;
        }
        // reconstruct: uA = u_{2bi}, uB = P1 - P0 = u_{2bi+1}
#pragma unroll
        for (int k = 0; k < 8; k++) uB[k] -= uA[k];

        // agreement dots
        float dA = 0.0f, dB = 0.0f;
#pragma unroll
        for (int k = 0; k < 8; k++) { dA += v_r[k]*uA[k]; dB += v_r[k]*uB[k]; }
        dA += __shfl_xor_sync(0xffffffffu, dA, 1);
        dA += __shfl_xor_sync(0xffffffffu, dA, 2);
        dB += __shfl_xor_sync(0xffffffffu, dB, 1);
        dB += __shfl_xor_sync(0xffffffffu, dB, 2);

        if (pass == 2) { dA += blpA; dB += blpB; }
        else if (gl == 0) {
            BL[(size_t)(2*bi)     * CJ] = dA;
            BL[(size_t)(2*bi + 1) * CJ] = dB;
        }

        // softmax over j, alpha=8, no max shift (logits bounded; fp32-safe)
        const float eA = exp2f(dA * 11.541560327111707f);
        const float eB = exp2f(dB * 11.541560327111707f);

        float esA = eA, esB = eB;
#pragma unroll
        for (int o = 4; o <= 16; o <<= 1) {
            esA += __shfl_xor_sync(0xffffffffu, esA, o);
            esB += __shfl_xor_sync(0xffffffffu, esB, o);
        }
        const int pb = bi & 1;
        if (l == 0) { red_sum[pb][0][wp] = esA; red_sum[pb][1][wp] = esB; }
        __syncthreads();

        const float4* rs = (const float4*)&red_sum[pb][0][0];
        float4 r0 = rs[0], r1 = rs[1], r2 = rs[2], r3 = rs[3];
        const float totA = ((r0.x + r0.y) + (r0.z + r0.w)) +
                           ((r1.x + r1.y) + (r1.z + r1.w));
        const float totB = ((r2.x + r2.y) + (r2.z + r2.w)) +
                           ((r3.x + r3.y) + (r3.z + r3.w));

        const float ccA = __fdividef(64.0f * eA, totA);
        const float ccB = __fdividef(64.0f * eB, totB);
#pragma unroll
        for (int k = 0; k < 8; k++) s_loc[k] += ccA * uA[k] + ccB * uB[k];

        A = C; B = D;
    }

#pragma unroll
    for (int k = 0; k < 8; k++)
        atomicAdd(&g_s[b * JM + 8*t + k], s_loc[k]);
}

// ---------------------------------------------------------------------------
// Squash: v = (|s|^2/(1+|s|^2)) * s * rsqrt(|s|^2 + eps). Re-zeroes g_s.
// ---------------------------------------------------------------------------
__global__ void __launch_bounds__(512) k_squash(float* dst)
{
    const int t    = threadIdx.x;
    const int gw   = blockIdx.x * 16 + (t >> 5);
    const int lane = t & 31;
    const int b    = gw >> 6;
    const int j    = gw & 63;
    const int idx  = b * JM + j * NJ + lane;

    const float s = g_s[idx];
    float sq = s * s;
#pragma unroll
    for (int o = 16; o > 0; o >>= 1)
        sq += __shfl_xor_sync(0xffffffffu, sq, o);

    const float coef = (sq / (1.0f + sq)) * rsqrtf(sq + 1e-7f);
    float* out = dst ? dst : g_v;
    out[idx] = s * coef;
    g_s[idx] = 0.0f;
}

// ---------------------------------------------------------------------------
extern "C" void kernel_launch(void* const* d_in, const int* in_sizes, int n_in,
                              void* d_out, int out_size)
{
    const float* X = (const float*)d_in[0];
    const float* W = (const float*)d_in[1];
    if (n_in >= 2 && in_sizes[0] > in_sizes[1]) {   // defensive order check
        const float* tmp = X; X = W; W = tmp;
    }
    float* out = (float*)d_out;

    k_u_prefix<<<K1_NBLK, 512>>>(X, W);
    k_s0_reduce<<<512, 256>>>();
    k_squash<<<64, 512>>>(nullptr);                 // v0, zero g_s
    k_route<<<dim3(RT_NIB, BB), 256>>>(1);
    k_squash<<<64, 512>>>(nullptr);                 // v1, zero g_s
    k_route<<<dim3(RT_NIB, BB), 256>>>(2);
    k_squash<<<64, 512>>>(out);                     // v2 -> output, zero g_s
    (void)out_size;
}